// round 1
// baseline (speedup 1.0000x reference)
#include <cuda_runtime.h>
#include <cuda_bf16.h>
#include <cstdint>

#define N_EMBED 384
#define NUM_EXPERTS 8
#define TOK_PER_BLK 128
#define KC 32            // k-chunk staged in smem
#define PITCH 36         // floats per token row in smem (gcd(36,32)=4; STS.128 conflict-free)
#define NCHUNK (N_EMBED / KC)

__device__ __forceinline__ void ffma2(unsigned long long& a, unsigned long long b, unsigned long long c) {
    asm("fma.rn.f32x2 %0, %1, %2, %0;" : "+l"(a) : "l"(b), "l"(c));
}
__device__ __forceinline__ unsigned long long bcast2(float v) {
    unsigned long long r;
    asm("mov.b64 %0, {%1, %1};" : "=l"(r) : "f"(v));
    return r;
}
__device__ __forceinline__ void unpack2(unsigned long long a, float& lo, float& hi) {
    asm("mov.b64 {%0, %1}, %2;" : "=f"(lo), "=f"(hi) : "l"(a));
}

__global__ __launch_bounds__(TOK_PER_BLK)
void noisy_topk_router_kernel(
    const float* __restrict__ x,        // [n_tok, 384]
    const float* __restrict__ noise,    // [n_tok, 8]
    const float* __restrict__ w_route,  // [8, 384]
    const float* __restrict__ b_route,  // [8]
    const float* __restrict__ w_noise,  // [8, 384]
    const float* __restrict__ b_noise,  // [8]
    float* __restrict__ out,            // [n_tok*8] router + optionally [n_tok*2] indices
    int n_tok, int write_idx)
{
    // ws: per expert e, per dim d: f32x2 (w_route[e][d], w_noise[e][d])  -> 24 KB
    __shared__ float2 ws[NUM_EXPERTS * N_EMBED];
    __shared__ float xs[TOK_PER_BLK * PITCH];   // 18 KB
    __shared__ float sb[2 * NUM_EXPERTS];

    const int tid = threadIdx.x;
    const int t0  = blockIdx.x * TOK_PER_BLK;
    const int t   = t0 + tid;

    // Pack weights into smem (layout index i == e*384+d for both tensors)
    for (int i = tid; i < NUM_EXPERTS * N_EMBED; i += TOK_PER_BLK)
        ws[i] = make_float2(w_route[i], w_noise[i]);
    if (tid < NUM_EXPERTS)           sb[tid] = b_route[tid];
    else if (tid < 2 * NUM_EXPERTS)  sb[tid] = b_noise[tid - NUM_EXPERTS];

    unsigned long long acc[NUM_EXPERTS];
#pragma unroll
    for (int e = 0; e < NUM_EXPERTS; e++) acc[e] = 0ull;

    const float* wsf = reinterpret_cast<const float*>(ws);

    for (int c = 0; c < NCHUNK; c++) {
        __syncthreads();  // prev chunk consumed (and ws/sb ready on c==0)

        // Stage 128 tokens x 32 floats, coalesced float4 LDG -> STS.128
#pragma unroll
        for (int r = 0; r < (TOK_PER_BLK * KC / 4) / TOK_PER_BLK; r++) {
            int idx = tid + r * TOK_PER_BLK;           // 0..1023
            int tok = idx >> 3;                        // 8 float4 per token-chunk
            int q   = idx & 7;
            if (t0 + tok < n_tok) {
                float4 v = *reinterpret_cast<const float4*>(
                    x + (size_t)(t0 + tok) * N_EMBED + c * KC + q * 4);
                *reinterpret_cast<float4*>(&xs[tok * PITCH + q * 4]) = v;
            }
        }
        __syncthreads();

        // Compute: 16 dims, 2 at a time; weights via broadcast LDS.128
#pragma unroll
        for (int j = 0; j < KC; j += 2) {
            float2 xv = *reinterpret_cast<const float2*>(&xs[tid * PITCH + j]);
            unsigned long long xlo = bcast2(xv.x);
            unsigned long long xhi = bcast2(xv.y);
            const int d = c * KC + j;
#pragma unroll
            for (int e = 0; e < NUM_EXPERTS; e++) {
                ulonglong2 w = *reinterpret_cast<const ulonglong2*>(&wsf[(e * N_EMBED + d) * 2]);
                ffma2(acc[e], xlo, w.x);
                ffma2(acc[e], xhi, w.y);
            }
        }
    }

    if (t >= n_tok) return;

    // Epilogue
    const float4* np = reinterpret_cast<const float4*>(noise + (size_t)t * NUM_EXPERTS);
    float4 nz0 = np[0], nz1 = np[1];
    float nz[NUM_EXPERTS] = {nz0.x, nz0.y, nz0.z, nz0.w, nz1.x, nz1.y, nz1.z, nz1.w};

    float v[NUM_EXPERTS];
#pragma unroll
    for (int e = 0; e < NUM_EXPERTS; e++) {
        float lg, nl;
        unpack2(acc[e], lg, nl);
        lg += sb[e];
        nl += sb[NUM_EXPERTS + e];
        // jax.nn.softplus: max(x,0) + log1p(exp(-|x|))
        float sp = fmaxf(nl, 0.0f) + log1pf(expf(-fabsf(nl)));
        v[e] = lg + nz[e] * sp;
    }

    // top-2, first-occurrence tie-break (matches jax.lax.top_k)
    float v0 = v[0]; int i0 = 0;
#pragma unroll
    for (int e = 1; e < NUM_EXPERTS; e++)
        if (v[e] > v0) { v0 = v[e]; i0 = e; }
    float v1 = -3.402823466e+38f; int i1 = 0;
#pragma unroll
    for (int e = 0; e < NUM_EXPERTS; e++) {
        bool take = (e != i0) && (v[e] > v1);
        if (take) { v1 = v[e]; i1 = e; }
    }

    // softmax over the 2 kept logits (others are exactly 0)
    float e1 = expf(v1 - v0);
    float inv = 1.0f / (1.0f + e1);
    float p0 = inv, p1 = e1 * inv;

    float o[NUM_EXPERTS];
#pragma unroll
    for (int e = 0; e < NUM_EXPERTS; e++)
        o[e] = (e == i0) ? p0 : ((e == i1) ? p1 : 0.0f);

    float4* op = reinterpret_cast<float4*>(out + (size_t)t * NUM_EXPERTS);
    op[0] = make_float4(o[0], o[1], o[2], o[3]);
    op[1] = make_float4(o[4], o[5], o[6], o[7]);

    if (write_idx) {
        float2* ip = reinterpret_cast<float2*>(out + (size_t)n_tok * NUM_EXPERTS);
        ip[t] = make_float2((float)i0, (float)i1);
    }
}

extern "C" void kernel_launch(void* const* d_in, const int* in_sizes, int n_in,
                              void* d_out, int out_size) {
    const float* x       = (const float*)d_in[0];
    const float* noise   = (const float*)d_in[1];
    const float* w_route = (const float*)d_in[2];
    const float* b_route = (const float*)d_in[3];
    const float* w_noise = (const float*)d_in[4];
    const float* b_noise = (const float*)d_in[5];
    float* out = (float*)d_out;

    int n_tok = in_sizes[0] / N_EMBED;
    int write_idx = (out_size >= n_tok * NUM_EXPERTS + n_tok * 2) ? 1 : 0;

    int grid = (n_tok + TOK_PER_BLK - 1) / TOK_PER_BLK;
    noisy_topk_router_kernel<<<grid, TOK_PER_BLK>>>(
        x, noise, w_route, b_route, w_noise, b_noise, out, n_tok, write_idx);
}

// round 2
// speedup vs baseline: 1.0419x; 1.0419x over previous
#include <cuda_runtime.h>
#include <cuda_bf16.h>
#include <cstdint>

#define N_EMBED 384
#define NUM_EXPERTS 8
#define TOK_PER_BLK 128
#define KC 32            // k-chunk staged in smem
#define PITCH 36         // floats per token row in smem (odd multiple of 4: conflict-free .128 phases)
#define NCHUNK (N_EMBED / KC)

__device__ __forceinline__ void ffma2(unsigned long long& a, unsigned long long b, unsigned long long c) {
    asm("fma.rn.f32x2 %0, %1, %2, %0;" : "+l"(a) : "l"(b), "l"(c));
}
__device__ __forceinline__ unsigned long long bcast2(float v) {
    unsigned long long r;
    asm("mov.b64 %0, {%1, %1};" : "=l"(r) : "f"(v));
    return r;
}
__device__ __forceinline__ unsigned long long pack2(float lo, float hi) {
    unsigned long long r;
    asm("mov.b64 %0, {%1, %2};" : "=l"(r) : "f"(lo), "f"(hi));
    return r;
}
__device__ __forceinline__ void unpack2(unsigned long long a, float& lo, float& hi) {
    asm("mov.b64 {%0, %1}, %2;" : "=f"(lo), "=f"(hi) : "l"(a));
}

__global__ __launch_bounds__(TOK_PER_BLK, 4)
void noisy_topk_router_kernel(
    const float* __restrict__ x,        // [n_tok, 384]
    const float* __restrict__ noise,    // [n_tok, 8]
    const float* __restrict__ w_route,  // [8, 384]
    const float* __restrict__ b_route,  // [8]
    const float* __restrict__ w_noise,  // [8, 384]
    const float* __restrict__ b_noise,  // [8]
    float* __restrict__ out,            // [n_tok*8] router + optionally [n_tok*2] indices
    int n_tok, int write_idx)
{
    // ws: per expert e, per dim d: f32x2 (w_route[e][d], w_noise[e][d])  -> 24 KB
    __shared__ float2 ws[NUM_EXPERTS * N_EMBED];
    __shared__ float xs[TOK_PER_BLK * PITCH];   // 18 KB, single buffer (regs are 2nd buffer)
    __shared__ float sb[2 * NUM_EXPERTS];

    const int tid = threadIdx.x;
    const int t0  = blockIdx.x * TOK_PER_BLK;
    const int t   = t0 + tid;
    const bool full = (t0 + TOK_PER_BLK <= n_tok);

    // Pack weights into smem (layout index i == e*384+d for both tensors)
    for (int i = tid; i < NUM_EXPERTS * N_EMBED; i += TOK_PER_BLK)
        ws[i] = make_float2(w_route[i], w_noise[i]);
    if (tid < NUM_EXPERTS)           sb[tid] = b_route[tid];
    else if (tid < 2 * NUM_EXPERTS)  sb[tid] = b_noise[tid - NUM_EXPERTS];

    // staging role: thread covers float4 #tid, #tid+128, ... of the 1024 per chunk
    const int s_tok = tid >> 3;                 // base token for r=0; general: (tid + r*128)>>3
    const int s_q   = tid & 7;
    (void)s_tok; (void)s_q;

    float4 pf[8];

    // ---- prologue: prefetch + stage chunk 0 ----
#pragma unroll
    for (int r = 0; r < 8; r++) {
        int idx = tid + r * TOK_PER_BLK;
        int tok = idx >> 3, q = idx & 7;
        if (full || (t0 + tok < n_tok))
            pf[r] = *reinterpret_cast<const float4*>(
                x + (size_t)(t0 + tok) * N_EMBED + q * 4);
    }
#pragma unroll
    for (int r = 0; r < 8; r++) {
        int idx = tid + r * TOK_PER_BLK;
        int tok = idx >> 3, q = idx & 7;
        *reinterpret_cast<float4*>(&xs[tok * PITCH + q * 4]) = pf[r];
    }
    __syncthreads();   // ws, sb, xs(chunk 0) all visible

    unsigned long long acc[NUM_EXPERTS];
#pragma unroll
    for (int e = 0; e < NUM_EXPERTS; e++)
        acc[e] = pack2(sb[e], sb[NUM_EXPERTS + e]);   // fold biases in

    const float* wsf = reinterpret_cast<const float*>(ws);

    for (int c = 0; c < NCHUNK; c++) {
        // prefetch chunk c+1 into registers (overlaps with compute below)
        if (c + 1 < NCHUNK) {
#pragma unroll
            for (int r = 0; r < 8; r++) {
                int idx = tid + r * TOK_PER_BLK;
                int tok = idx >> 3, q = idx & 7;
                if (full || (t0 + tok < n_tok))
                    pf[r] = *reinterpret_cast<const float4*>(
                        x + (size_t)(t0 + tok) * N_EMBED + (c + 1) * KC + q * 4);
            }
        }

        // compute chunk c: 8 steps of 4 dims
#pragma unroll
        for (int j = 0; j < KC; j += 4) {
            float4 xv = *reinterpret_cast<const float4*>(&xs[tid * PITCH + j]);
            unsigned long long x0 = bcast2(xv.x);
            unsigned long long x1 = bcast2(xv.y);
            unsigned long long x2 = bcast2(xv.z);
            unsigned long long x3 = bcast2(xv.w);
            const int d = c * KC + j;
#pragma unroll
            for (int e = 0; e < NUM_EXPERTS; e++) {
                ulonglong2 wa = *reinterpret_cast<const ulonglong2*>(&wsf[(e * N_EMBED + d) * 2]);
                ulonglong2 wb = *reinterpret_cast<const ulonglong2*>(&wsf[(e * N_EMBED + d + 2) * 2]);
                ffma2(acc[e], x0, wa.x);
                ffma2(acc[e], x1, wa.y);
                ffma2(acc[e], x2, wb.x);
                ffma2(acc[e], x3, wb.y);
            }
        }

        if (c + 1 < NCHUNK) {
            __syncthreads();   // all readers of xs done
#pragma unroll
            for (int r = 0; r < 8; r++) {
                int idx = tid + r * TOK_PER_BLK;
                int tok = idx >> 3, q = idx & 7;
                *reinterpret_cast<float4*>(&xs[tok * PITCH + q * 4]) = pf[r];
            }
            __syncthreads();   // chunk c+1 visible
        }
    }

    if (t >= n_tok) return;

    // ---- epilogue ----
    const float4* np = reinterpret_cast<const float4*>(noise + (size_t)t * NUM_EXPERTS);
    float4 nz0 = np[0], nz1 = np[1];
    float nz[NUM_EXPERTS] = {nz0.x, nz0.y, nz0.z, nz0.w, nz1.x, nz1.y, nz1.z, nz1.w};

    float v[NUM_EXPERTS];
#pragma unroll
    for (int e = 0; e < NUM_EXPERTS; e++) {
        float lg, nl;
        unpack2(acc[e], lg, nl);
        // jax.nn.softplus: max(x,0) + log1p(exp(-|x|))
        float sp = fmaxf(nl, 0.0f) + log1pf(expf(-fabsf(nl)));
        v[e] = lg + nz[e] * sp;
    }

    // top-2, first-occurrence tie-break (matches jax.lax.top_k)
    float v0 = v[0]; int i0 = 0;
#pragma unroll
    for (int e = 1; e < NUM_EXPERTS; e++)
        if (v[e] > v0) { v0 = v[e]; i0 = e; }
    float v1 = -3.402823466e+38f; int i1 = 0;
#pragma unroll
    for (int e = 0; e < NUM_EXPERTS; e++) {
        bool take = (e != i0) && (v[e] > v1);
        if (take) { v1 = v[e]; i1 = e; }
    }

    // softmax over the 2 kept logits (others are exactly 0)
    float e1 = expf(v1 - v0);
    float inv = 1.0f / (1.0f + e1);
    float p0 = inv, p1 = e1 * inv;

    float o[NUM_EXPERTS];
#pragma unroll
    for (int e = 0; e < NUM_EXPERTS; e++)
        o[e] = (e == i0) ? p0 : ((e == i1) ? p1 : 0.0f);

    float4* op = reinterpret_cast<float4*>(out + (size_t)t * NUM_EXPERTS);
    op[0] = make_float4(o[0], o[1], o[2], o[3]);
    op[1] = make_float4(o[4], o[5], o[6], o[7]);

    if (write_idx) {
        float2* ip = reinterpret_cast<float2*>(out + (size_t)n_tok * NUM_EXPERTS);
        ip[t] = make_float2((float)i0, (float)i1);
    }
}

extern "C" void kernel_launch(void* const* d_in, const int* in_sizes, int n_in,
                              void* d_out, int out_size) {
    const float* x       = (const float*)d_in[0];
    const float* noise   = (const float*)d_in[1];
    const float* w_route = (const float*)d_in[2];
    const float* b_route = (const float*)d_in[3];
    const float* w_noise = (const float*)d_in[4];
    const float* b_noise = (const float*)d_in[5];
    float* out = (float*)d_out;

    int n_tok = in_sizes[0] / N_EMBED;
    int write_idx = (out_size >= n_tok * NUM_EXPERTS + n_tok * 2) ? 1 : 0;

    int grid = (n_tok + TOK_PER_BLK - 1) / TOK_PER_BLK;
    noisy_topk_router_kernel<<<grid, TOK_PER_BLK>>>(
        x, noise, w_route, b_route, w_noise, b_noise, out, n_tok, write_idx);
}

// round 3
// speedup vs baseline: 1.3128x; 1.2600x over previous
#include <cuda_runtime.h>
#include <cuda_bf16.h>
#include <cstdint>

#define N_EMBED 384
#define NUM_EXPERTS 8
#define THREADS 128
#define TPT 4                       // tokens per thread
#define TOK_PER_BLK (THREADS * TPT) // 512
#define KC 32                       // k-chunk staged in smem
#define PITCH 36                    // floats per token row (conflict-free .128 phases)
#define NCHUNK (N_EMBED / KC)       // 12

#define WS_BYTES (NUM_EXPERTS * N_EMBED * 8)          // 24576
#define XS_OFF   (WS_BYTES + 64)                      // 24640 (sb in the 64B gap)
#define XS_BUF_FLOATS (TOK_PER_BLK * PITCH)           // 18432 floats = 73728 B
#define SMEM_TOTAL (XS_OFF + 2 * XS_BUF_FLOATS * 4)   // 172096 B

typedef unsigned long long ull;

__device__ __forceinline__ void ffma2(ull& a, ull b, ull c) {
    asm("fma.rn.f32x2 %0, %1, %2, %0;" : "+l"(a) : "l"(b), "l"(c));
}
__device__ __forceinline__ ull bcast2(float v) {
    ull r; asm("mov.b64 %0, {%1, %1};" : "=l"(r) : "f"(v)); return r;
}
__device__ __forceinline__ ull pack2(float lo, float hi) {
    ull r; asm("mov.b64 %0, {%1, %2};" : "=l"(r) : "f"(lo), "f"(hi)); return r;
}
__device__ __forceinline__ void unpack2(ull a, float& lo, float& hi) {
    asm("mov.b64 {%0, %1}, %2;" : "=f"(lo), "=f"(hi) : "l"(a));
}
__device__ __forceinline__ uint32_t smem_u32(const void* p) {
    return (uint32_t)__cvta_generic_to_shared(p);
}
__device__ __forceinline__ void cp16(uint32_t dst, const void* src, int pred) {
    asm volatile(
        "{ .reg .pred q; setp.ne.b32 q, %2, 0;\n\t"
        "@q cp.async.ca.shared.global [%0], [%1], 16; }"
        :: "r"(dst), "l"(src), "r"(pred));
}

__global__ __launch_bounds__(THREADS)
void noisy_topk_router_kernel(
    const float* __restrict__ x,        // [n_tok, 384]
    const float* __restrict__ noise,    // [n_tok, 8]
    const float* __restrict__ w_route,  // [8, 384]
    const float* __restrict__ b_route,  // [8]
    const float* __restrict__ w_noise,  // [8, 384]
    const float* __restrict__ b_noise,  // [8]
    float* __restrict__ out,
    int n_tok, int write_idx)
{
    extern __shared__ char smem[];
    float2* ws = reinterpret_cast<float2*>(smem);                 // (route, noise) per [e][d]
    float*  sb = reinterpret_cast<float*>(smem + WS_BYTES);       // 16 biases
    float*  xs = reinterpret_cast<float*>(smem + XS_OFF);         // [2][512*36]

    const int tid = threadIdx.x;
    const int t0  = blockIdx.x * TOK_PER_BLK;

    // pack weights into smem
    for (int i = tid; i < NUM_EXPERTS * N_EMBED; i += THREADS)
        ws[i] = make_float2(w_route[i], w_noise[i]);
    if (tid < NUM_EXPERTS)           sb[tid] = b_route[tid];
    else if (tid < 2 * NUM_EXPERTS)  sb[tid] = b_noise[tid - NUM_EXPERTS];

    // ---- async staging of x chunks ----
    auto stage = [&](int c) {
        float* dst = xs + (c & 1) * XS_BUF_FLOATS;
#pragma unroll
        for (int r = 0; r < TOK_PER_BLK * (KC / 4) / THREADS; r++) {   // 32
            int idx = tid + r * THREADS;
            int tok = idx >> 3, q = idx & 7;
            const float* src = x + (size_t)(t0 + tok) * N_EMBED + c * KC + q * 4;
            cp16(smem_u32(dst + tok * PITCH + q * 4), src, (t0 + tok < n_tok) ? 1 : 0);
        }
        asm volatile("cp.async.commit_group;" ::: "memory");
    };

    stage(0);
    stage(1);
    asm volatile("cp.async.wait_group 1;" ::: "memory");   // chunk 0 landed (this thread)
    __syncthreads();                                       // xs c0 + ws + sb visible

    ull acc[TPT][NUM_EXPERTS];
#pragma unroll
    for (int k = 0; k < TPT; k++)
#pragma unroll
        for (int e = 0; e < NUM_EXPERTS; e++)
            acc[k][e] = pack2(sb[e], sb[NUM_EXPERTS + e]);   // fold biases in

    const float* wsf = reinterpret_cast<const float*>(ws);

    for (int c = 0; c < NCHUNK; c++) {
        const float* buf = xs + (c & 1) * XS_BUF_FLOATS;
#pragma unroll
        for (int j = 0; j < KC; j += 4) {
            ull xb[TPT][4];
#pragma unroll
            for (int k = 0; k < TPT; k++) {
                float4 xv = *reinterpret_cast<const float4*>(&buf[(tid + k * THREADS) * PITCH + j]);
                xb[k][0] = bcast2(xv.x); xb[k][1] = bcast2(xv.y);
                xb[k][2] = bcast2(xv.z); xb[k][3] = bcast2(xv.w);
            }
            const int d = c * KC + j;
#pragma unroll
            for (int e = 0; e < NUM_EXPERTS; e++) {
                ulonglong2 wa = *reinterpret_cast<const ulonglong2*>(&wsf[(e * N_EMBED + d) * 2]);
                ulonglong2 wb = *reinterpret_cast<const ulonglong2*>(&wsf[(e * N_EMBED + d + 2) * 2]);
#pragma unroll
                for (int k = 0; k < TPT; k++) {
                    ffma2(acc[k][e], xb[k][0], wa.x);
                    ffma2(acc[k][e], xb[k][1], wa.y);
                    ffma2(acc[k][e], xb[k][2], wb.x);
                    ffma2(acc[k][e], xb[k][3], wb.y);
                }
            }
        }
        __syncthreads();   // everyone done reading buf (c&1)
        if (c + 2 < NCHUNK) stage(c + 2);
        else asm volatile("cp.async.commit_group;" ::: "memory");   // keep group count moving
        asm volatile("cp.async.wait_group 1;" ::: "memory");        // chunk c+1 landed
        __syncthreads();
    }

    // ---- epilogue per token ----
#pragma unroll
    for (int k = 0; k < TPT; k++) {
        int t = t0 + tid + k * THREADS;
        if (t >= n_tok) continue;

        const float4* np = reinterpret_cast<const float4*>(noise + (size_t)t * NUM_EXPERTS);
        float4 nz0 = np[0], nz1 = np[1];
        float nz[NUM_EXPERTS] = {nz0.x, nz0.y, nz0.z, nz0.w, nz1.x, nz1.y, nz1.z, nz1.w};

        float v[NUM_EXPERTS];
#pragma unroll
        for (int e = 0; e < NUM_EXPERTS; e++) {
            float lg, nl;
            unpack2(acc[k][e], lg, nl);
            // jax.nn.softplus: max(x,0) + log1p(exp(-|x|))
            float sp = fmaxf(nl, 0.0f) + log1pf(expf(-fabsf(nl)));
            v[e] = lg + nz[e] * sp;
        }

        // top-2, first-occurrence tie-break (matches jax.lax.top_k)
        float v0 = v[0]; int i0 = 0;
#pragma unroll
        for (int e = 1; e < NUM_EXPERTS; e++)
            if (v[e] > v0) { v0 = v[e]; i0 = e; }
        float v1 = -3.402823466e+38f; int i1 = 0;
#pragma unroll
        for (int e = 0; e < NUM_EXPERTS; e++) {
            bool take = (e != i0) && (v[e] > v1);
            if (take) { v1 = v[e]; i1 = e; }
        }

        float e1 = expf(v1 - v0);
        float inv = 1.0f / (1.0f + e1);
        float p0 = inv, p1 = e1 * inv;

        float o[NUM_EXPERTS];
#pragma unroll
        for (int e = 0; e < NUM_EXPERTS; e++)
            o[e] = (e == i0) ? p0 : ((e == i1) ? p1 : 0.0f);

        float4* op = reinterpret_cast<float4*>(out + (size_t)t * NUM_EXPERTS);
        op[0] = make_float4(o[0], o[1], o[2], o[3]);
        op[1] = make_float4(o[4], o[5], o[6], o[7]);

        if (write_idx) {
            float2* ip = reinterpret_cast<float2*>(out + (size_t)n_tok * NUM_EXPERTS);
            ip[t] = make_float2((float)i0, (float)i1);
        }
    }
}

extern "C" void kernel_launch(void* const* d_in, const int* in_sizes, int n_in,
                              void* d_out, int out_size) {
    const float* x       = (const float*)d_in[0];
    const float* noise   = (const float*)d_in[1];
    const float* w_route = (const float*)d_in[2];
    const float* b_route = (const float*)d_in[3];
    const float* w_noise = (const float*)d_in[4];
    const float* b_noise = (const float*)d_in[5];
    float* out = (float*)d_out;

    int n_tok = in_sizes[0] / N_EMBED;
    int write_idx = (out_size >= n_tok * NUM_EXPERTS + n_tok * 2) ? 1 : 0;

    cudaFuncSetAttribute(noisy_topk_router_kernel,
                         cudaFuncAttributeMaxDynamicSharedMemorySize, SMEM_TOTAL);

    int grid = (n_tok + TOK_PER_BLK - 1) / TOK_PER_BLK;
    noisy_topk_router_kernel<<<grid, THREADS, SMEM_TOTAL>>>(
        x, noise, w_route, b_route, w_noise, b_noise, out, n_tok, write_idx);
}

// round 4
// speedup vs baseline: 1.4519x; 1.1060x over previous
#include <cuda_runtime.h>
#include <cuda_bf16.h>
#include <cstdint>

#define N_EMBED 384
#define NUM_EXPERTS 8
#define THREADS 128
#define TPT 2                       // tokens per thread
#define TOK_PER_BLK (THREADS * TPT) // 256
#define KC 32                       // k-chunk staged in smem
#define PITCH 36                    // floats per token row (conflict-free .128 phases)
#define NCHUNK (N_EMBED / KC)       // 12

#define WS_BYTES (NUM_EXPERTS * N_EMBED * 8)          // 24576
#define XS_OFF   (WS_BYTES + 64)                      // 24640 (sb in the 64B gap)
#define XS_BUF_FLOATS (TOK_PER_BLK * PITCH)           // 9216 floats = 36864 B
#define SMEM_TOTAL (XS_OFF + 2 * XS_BUF_FLOATS * 4)   // 98368 B  -> 2 CTAs/SM

typedef unsigned long long ull;

__device__ __forceinline__ void ffma2(ull& a, ull b, ull c) {
    asm("fma.rn.f32x2 %0, %1, %2, %0;" : "+l"(a) : "l"(b), "l"(c));
}
__device__ __forceinline__ ull bcast2(float v) {
    ull r; asm("mov.b64 %0, {%1, %1};" : "=l"(r) : "f"(v)); return r;
}
__device__ __forceinline__ ull pack2(float lo, float hi) {
    ull r; asm("mov.b64 %0, {%1, %2};" : "=l"(r) : "f"(lo), "f"(hi)); return r;
}
__device__ __forceinline__ void unpack2(ull a, float& lo, float& hi) {
    asm("mov.b64 {%0, %1}, %2;" : "=f"(lo), "=f"(hi) : "l"(a));
}
__device__ __forceinline__ uint32_t smem_u32(const void* p) {
    return (uint32_t)__cvta_generic_to_shared(p);
}
__device__ __forceinline__ void cp16(uint32_t dst, const void* src, int pred) {
    asm volatile(
        "{ .reg .pred q; setp.ne.b32 q, %2, 0;\n\t"
        "@q cp.async.ca.shared.global [%0], [%1], 16; }"
        :: "r"(dst), "l"(src), "r"(pred));
}

__global__ __launch_bounds__(THREADS, 2)
void noisy_topk_router_kernel(
    const float* __restrict__ x,        // [n_tok, 384]
    const float* __restrict__ noise,    // [n_tok, 8]
    const float* __restrict__ w_route,  // [8, 384]
    const float* __restrict__ b_route,  // [8]
    const float* __restrict__ w_noise,  // [8, 384]
    const float* __restrict__ b_noise,  // [8]
    float* __restrict__ out,
    int n_tok, int write_idx)
{
    extern __shared__ char smem[];
    float2* ws = reinterpret_cast<float2*>(smem);                 // (route, noise) per [e][d]
    float*  sb = reinterpret_cast<float*>(smem + WS_BYTES);       // 16 biases
    float*  xs = reinterpret_cast<float*>(smem + XS_OFF);         // [2][256*36]

    const int tid = threadIdx.x;
    const int t0  = blockIdx.x * TOK_PER_BLK;

    // pack weights into smem
    for (int i = tid; i < NUM_EXPERTS * N_EMBED; i += THREADS)
        ws[i] = make_float2(w_route[i], w_noise[i]);
    if (tid < NUM_EXPERTS)           sb[tid] = b_route[tid];
    else if (tid < 2 * NUM_EXPERTS)  sb[tid] = b_noise[tid - NUM_EXPERTS];

    // ---- async staging of x chunks (16 float4 per thread per chunk) ----
    auto stage = [&](int c) {
        float* dst = xs + (c & 1) * XS_BUF_FLOATS;
#pragma unroll
        for (int r = 0; r < TOK_PER_BLK * (KC / 4) / THREADS; r++) {   // 16
            int idx = tid + r * THREADS;
            int tok = idx >> 3, q = idx & 7;
            const float* src = x + (size_t)(t0 + tok) * N_EMBED + c * KC + q * 4;
            cp16(smem_u32(dst + tok * PITCH + q * 4), src, (t0 + tok < n_tok) ? 1 : 0);
        }
        asm volatile("cp.async.commit_group;" ::: "memory");
    };

    stage(0);
    stage(1);
    asm volatile("cp.async.wait_group 1;" ::: "memory");   // chunk 0 landed (this thread)
    __syncthreads();                                       // xs c0 + ws + sb visible

    ull acc[TPT][NUM_EXPERTS];
#pragma unroll
    for (int k = 0; k < TPT; k++)
#pragma unroll
        for (int e = 0; e < NUM_EXPERTS; e++)
            acc[k][e] = pack2(sb[e], sb[NUM_EXPERTS + e]);   // fold biases in

    const float* wsf = reinterpret_cast<const float*>(ws);

    for (int c = 0; c < NCHUNK; c++) {
        const float* buf = xs + (c & 1) * XS_BUF_FLOATS;
#pragma unroll
        for (int j = 0; j < KC; j += 4) {
            ull xb[TPT][4];
#pragma unroll
            for (int k = 0; k < TPT; k++) {
                float4 xv = *reinterpret_cast<const float4*>(&buf[(tid + k * THREADS) * PITCH + j]);
                xb[k][0] = bcast2(xv.x); xb[k][1] = bcast2(xv.y);
                xb[k][2] = bcast2(xv.z); xb[k][3] = bcast2(xv.w);
            }
            const int d = c * KC + j;
#pragma unroll
            for (int e = 0; e < NUM_EXPERTS; e++) {
                ulonglong2 wa = *reinterpret_cast<const ulonglong2*>(&wsf[(e * N_EMBED + d) * 2]);
                ulonglong2 wb = *reinterpret_cast<const ulonglong2*>(&wsf[(e * N_EMBED + d + 2) * 2]);
#pragma unroll
                for (int k = 0; k < TPT; k++) {
                    ffma2(acc[k][e], xb[k][0], wa.x);
                    ffma2(acc[k][e], xb[k][1], wa.y);
                    ffma2(acc[k][e], xb[k][2], wb.x);
                    ffma2(acc[k][e], xb[k][3], wb.y);
                }
            }
        }
        __syncthreads();   // everyone done reading buf (c&1)
        if (c + 2 < NCHUNK) stage(c + 2);
        else asm volatile("cp.async.commit_group;" ::: "memory");   // keep group count moving
        asm volatile("cp.async.wait_group 1;" ::: "memory");        // chunk c+1 landed
        __syncthreads();
    }

    // ---- epilogue per token ----
#pragma unroll
    for (int k = 0; k < TPT; k++) {
        int t = t0 + tid + k * THREADS;
        if (t >= n_tok) continue;

        const float4* np = reinterpret_cast<const float4*>(noise + (size_t)t * NUM_EXPERTS);
        float4 nz0 = np[0], nz1 = np[1];
        float nz[NUM_EXPERTS] = {nz0.x, nz0.y, nz0.z, nz0.w, nz1.x, nz1.y, nz1.z, nz1.w};

        float v[NUM_EXPERTS];
#pragma unroll
        for (int e = 0; e < NUM_EXPERTS; e++) {
            float lg, nl;
            unpack2(acc[k][e], lg, nl);
            // jax.nn.softplus: max(x,0) + log1p(exp(-|x|))
            float sp = fmaxf(nl, 0.0f) + log1pf(expf(-fabsf(nl)));
            v[e] = lg + nz[e] * sp;
        }

        // top-2, first-occurrence tie-break (matches jax.lax.top_k)
        float v0 = v[0]; int i0 = 0;
#pragma unroll
        for (int e = 1; e < NUM_EXPERTS; e++)
            if (v[e] > v0) { v0 = v[e]; i0 = e; }
        float v1 = -3.402823466e+38f; int i1 = 0;
#pragma unroll
        for (int e = 0; e < NUM_EXPERTS; e++) {
            bool take = (e != i0) && (v[e] > v1);
            if (take) { v1 = v[e]; i1 = e; }
        }

        float e1 = expf(v1 - v0);
        float inv = 1.0f / (1.0f + e1);
        float p0 = inv, p1 = e1 * inv;

        float o[NUM_EXPERTS];
#pragma unroll
        for (int e = 0; e < NUM_EXPERTS; e++)
            o[e] = (e == i0) ? p0 : ((e == i1) ? p1 : 0.0f);

        float4* op = reinterpret_cast<float4*>(out + (size_t)t * NUM_EXPERTS);
        op[0] = make_float4(o[0], o[1], o[2], o[3]);
        op[1] = make_float4(o[4], o[5], o[6], o[7]);

        if (write_idx) {
            float2* ip = reinterpret_cast<float2*>(out + (size_t)n_tok * NUM_EXPERTS);
            ip[t] = make_float2((float)i0, (float)i1);
        }
    }
}

extern "C" void kernel_launch(void* const* d_in, const int* in_sizes, int n_in,
                              void* d_out, int out_size) {
    const float* x       = (const float*)d_in[0];
    const float* noise   = (const float*)d_in[1];
    const float* w_route = (const float*)d_in[2];
    const float* b_route = (const float*)d_in[3];
    const float* w_noise = (const float*)d_in[4];
    const float* b_noise = (const float*)d_in[5];
    float* out = (float*)d_out;

    int n_tok = in_sizes[0] / N_EMBED;
    int write_idx = (out_size >= n_tok * NUM_EXPERTS + n_tok * 2) ? 1 : 0;

    cudaFuncSetAttribute(noisy_topk_router_kernel,
                         cudaFuncAttributeMaxDynamicSharedMemorySize, SMEM_TOTAL);

    int grid = (n_tok + TOK_PER_BLK - 1) / TOK_PER_BLK;
    noisy_topk_router_kernel<<<grid, THREADS, SMEM_TOTAL>>>(
        x, noise, w_route, b_route, w_noise, b_noise, out, n_tok, write_idx);
}